// round 1
// baseline (speedup 1.0000x reference)
#include <cuda_runtime.h>

// QLSTM on GB300: one CTA per batch element, whole T=64 recurrence in-kernel.
// 4 statevectors (one per LSTM gate) of 1024 complex amps live in smem.
// 10 smem passes per circuit per step (vs 90 naive gates):
//   init(product state) + 4 rot passes (L1) + ring perm + 3 rot passes (L2)
//   + fused (wire9 gate + expectations) pass. L2 CNOT ring folded into
//   expectation parity masks. Swizzled smem + rotate-by-3 index scheme keeps
//   every pass conflict-free (2-phase float2 accesses).

#define TT 64
#define BB 256
#define DD 32
#define HH 10
#define NTH 512

// SU(2) gate:  a0' = alpha*a0 - conj(beta)*a1 ; a1' = beta*a0 + conj(alpha)*a1
__device__ __forceinline__ void su2(float2 &a0, float2 &a1,
                                    float ax, float ay, float bx, float by) {
    float n0x = ax*a0.x - ay*a0.y - bx*a1.x - by*a1.y;
    float n0y = ax*a0.y + ay*a0.x - bx*a1.y + by*a1.x;
    float n1x = bx*a0.x - by*a0.y + ax*a1.x + ay*a1.y;
    float n1y = bx*a0.y + by*a0.x + ax*a1.y - ay*a1.x;
    a0.x = n0x; a0.y = n0y; a1.x = n1x; a1.y = n1y;
}

__device__ __forceinline__ int sidx(int i) { return i ^ ((i >> 3) & 7); }

// Ring CNOT chain as GF(2)-linear map: y_w = x0^..^xw (w>=1), y_0 = x1^..^x9.
__device__ __forceinline__ int ring_map(int x) {
    int pref = x;
    pref ^= pref << 1;
    pref ^= pref << 2;
    pref ^= pref << 4;
    pref ^= pref << 8;
    return (pref & 0x3FE) | (((pref >> 9) ^ x) & 1);
}

// Apply NG gates at physical bits 0..NG-1 of each oct, then write indices
// rotated right by 3 (phys' = rotr10(phys,3)). Read & write swizzled.
template<int NG>
__device__ __forceinline__ void rot_pass(float2* __restrict__ svc, int g,
                                         float4 Ua, float4 Ub, float4 Uc) {
    const int rbase = g << 3;
    const int rsw   = g & 7;
    float2 a[8];
#pragma unroll
    for (int j = 0; j < 8; ++j) a[j] = svc[rbase | (j ^ rsw)];

    // gate at phys bit 0
    su2(a[0], a[1], Ua.x, Ua.y, Ua.z, Ua.w);
    su2(a[2], a[3], Ua.x, Ua.y, Ua.z, Ua.w);
    su2(a[4], a[5], Ua.x, Ua.y, Ua.z, Ua.w);
    su2(a[6], a[7], Ua.x, Ua.y, Ua.z, Ua.w);
    if (NG > 1) { // phys bit 1
        su2(a[0], a[2], Ub.x, Ub.y, Ub.z, Ub.w);
        su2(a[1], a[3], Ub.x, Ub.y, Ub.z, Ub.w);
        su2(a[4], a[6], Ub.x, Ub.y, Ub.z, Ub.w);
        su2(a[5], a[7], Ub.x, Ub.y, Ub.z, Ub.w);
    }
    if (NG > 2) { // phys bit 2
        su2(a[0], a[4], Uc.x, Uc.y, Uc.z, Uc.w);
        su2(a[1], a[5], Uc.x, Uc.y, Uc.z, Uc.w);
        su2(a[2], a[6], Uc.x, Uc.y, Uc.z, Uc.w);
        su2(a[3], a[7], Uc.x, Uc.y, Uc.z, Uc.w);
    }
    __syncthreads();
    const int wb0 = g ^ ((g >> 3) & 7);   // sidx(g | j<<7) = wb0 | j<<7
#pragma unroll
    for (int j = 0; j < 8; ++j) svc[wb0 | (j << 7)] = a[j];
    __syncthreads();
}

// Ring permutation pass: state read under rotation k=2, written at k'=0.
__device__ __forceinline__ void ring_pass(float2* __restrict__ svc, int g) {
    const int rbase = g << 3;
    const int rsw   = g & 7;
    float2 a[8];
    int    wa[8];
#pragma unroll
    for (int j = 0; j < 8; ++j) {
        a[j] = svc[rbase | (j ^ rsw)];
        int p = rbase | j;
        int x = ((p << 2) | (p >> 8)) & 1023;   // logical index (k=2)
        wa[j] = sidx(ring_map(x));
    }
    __syncthreads();
#pragma unroll
    for (int j = 0; j < 8; ++j) svc[wa[j]] = a[j];
    __syncthreads();
}

__global__ void __launch_bounds__(NTH, 2)
qlstm_kernel(const float* __restrict__ inputs,  // [T,B,D]
             const float* __restrict__ qparams, // [2,10,3]
             const float* __restrict__ Wf, const float* __restrict__ bf,
             const float* __restrict__ Wi, const float* __restrict__ bi,
             const float* __restrict__ Wg, const float* __restrict__ bg,
             const float* __restrict__ Wo, const float* __restrict__ bo,
             float* __restrict__ out)
{
    __shared__ float2 sv[4 * 1024];       // 4 statevectors, 32 KB
    __shared__ float  sW[4][HH][42];
    __shared__ float  sB[4][HH];
    __shared__ float4 sU[2][HH];          // fused RY*RX*RZ as SU(2) (alpha,beta)
    __shared__ float  enc_c[4][HH], enc_s[4][HH];
    __shared__ float  comb[42];
    __shared__ float  qexp[4][HH];
    __shared__ float  shx[HH], scx[HH];

    const int tid = threadIdx.x;
    const int b   = blockIdx.x;
    const int c   = tid >> 7;             // circuit (gate) 0..3: whole warps
    const int g   = tid & 127;            // oct index (phys bits 3..9)
    float2* svc = sv + (c << 10);

    // ---- one-time setup: weights, biases, fused rotation matrices ----
    for (int i = tid; i < 420; i += NTH) {
        ((float*)sW)[i]        = Wf[i];
        ((float*)sW)[420 + i]  = Wi[i];
        ((float*)sW)[840 + i]  = Wg[i];
        ((float*)sW)[1260 + i] = Wo[i];
    }
    if (tid < HH) {
        sB[0][tid] = bf[tid]; sB[1][tid] = bi[tid];
        sB[2][tid] = bg[tid]; sB[3][tid] = bo[tid];
        shx[tid] = 0.f; scx[tid] = 0.f;
    }
    if (tid < 20) {
        int l = tid / 10, w = tid % 10;
        float tz = qparams[(l*10 + w)*3 + 0];
        float tx = qparams[(l*10 + w)*3 + 1];
        float ty = qparams[(l*10 + w)*3 + 2];
        float c1, s1, c2, s2, c3, s3;
        sincosf(0.5f*tz, &s1, &c1);
        sincosf(0.5f*tx, &s2, &c2);
        sincosf(0.5f*ty, &s3, &c3);
        // A = RX*RZ : alpha=(c2c1, -c2s1), beta=(-s2s1, -s2c1)
        float aAx =  c2*c1, aAy = -c2*s1;
        float bAx = -s2*s1, bAy = -s2*c1;
        // U = RY*A  (RY: alpha=(c3,0), beta=(s3,0) both real)
        sU[l][w] = make_float4(c3*aAx - s3*bAx, c3*aAy - s3*bAy,
                               s3*aAx + c3*bAx, s3*aAy + c3*bAy);
    }
    __syncthreads();

    for (int t = 0; t < TT; ++t) {
        // ---- pre-activations + encoding angles ----
        if (tid < DD)            comb[tid] = inputs[((size_t)(t*BB) + b)*DD + tid];
        else if (tid < DD + HH)  comb[tid] = shx[tid - DD];
        if (tid < 40)            ((float*)qexp)[tid] = 0.f;
        __syncthreads();
        if (tid < 40) {
            int gg = tid / 10, h = tid % 10;
            const float* wrow = &sW[gg][h][0];
            float acc = sB[gg][h];
#pragma unroll
            for (int j = 0; j < 42; ++j) acc = fmaf(wrow[j], comb[j], acc);
            float cc, ss;
            sincosf(0.5f*acc, &ss, &cc);
            enc_c[gg][h] = cc; enc_s[gg][h] = ss;
        }
        __syncthreads();

        // ---- INIT pass: write encoded product state directly (k=0) ----
        {
            float f = 1.f;
#pragma unroll
            for (int w = 0; w < 7; ++w)
                f *= ((g >> w) & 1) ? enc_s[c][w + 3] : enc_c[c][w + 3];
            float c0 = enc_c[c][0], s0 = enc_s[c][0];
            float c1 = enc_c[c][1], s1 = enc_s[c][1];
            float c2 = enc_c[c][2], s2 = enc_s[c][2];
            float v[8];
            v[0] = f*c0*c1*c2; v[1] = f*s0*c1*c2; v[2] = f*c0*s1*c2; v[3] = f*s0*s1*c2;
            v[4] = f*c0*c1*s2; v[5] = f*s0*c1*s2; v[6] = f*c0*s1*s2; v[7] = f*s0*s1*s2;
            const int rbase = g << 3, rsw = g & 7;
#pragma unroll
            for (int j = 0; j < 8; ++j)
                svc[rbase | (j ^ rsw)] = make_float2(v[j], 0.f);
            __syncthreads();
        }

        // ---- layer 1 rotations (k: 0->3->6->9->2) ----
        rot_pass<3>(svc, g, sU[0][0], sU[0][1], sU[0][2]);
        rot_pass<3>(svc, g, sU[0][3], sU[0][4], sU[0][5]);
        rot_pass<3>(svc, g, sU[0][6], sU[0][7], sU[0][8]);
        rot_pass<1>(svc, g, sU[0][9], sU[0][9], sU[0][9]);
        // ---- layer 1 CNOT ring as one permutation pass (k=2 -> k=0) ----
        ring_pass(svc, g);
        // ---- layer 2 rotations, wires 0..8 (k: 0->3->6->9) ----
        rot_pass<3>(svc, g, sU[1][0], sU[1][1], sU[1][2]);
        rot_pass<3>(svc, g, sU[1][3], sU[1][4], sU[1][5]);
        rot_pass<3>(svc, g, sU[1][6], sU[1][7], sU[1][8]);

        // ---- final pass: wire-9 rotation + probs + <Z_w> with L2 ring
        //      folded into parity masks (k=9: phys bit0 = wire 9) ----
        {
            float acc[10];
#pragma unroll
            for (int w = 0; w < 10; ++w) acc[w] = 0.f;
            const int rbase = g << 3, rsw = g & 7;
            float4 U9 = sU[1][9];
#pragma unroll
            for (int j = 0; j < 8; j += 2) {
                float2 a0 = svc[rbase | ( j      ^ rsw)];
                float2 a1 = svc[rbase | ((j + 1) ^ rsw)];
                su2(a0, a1, U9.x, U9.y, U9.z, U9.w);
#pragma unroll
                for (int jj = 0; jj < 2; ++jj) {
                    float2 aa = jj ? a1 : a0;
                    int p = rbase | (j + jj);
                    int x = (p >> 1) | ((p & 1) << 9);   // logical index (k=9)
                    int y = ring_map(x);                 // post-ring bit values
                    float prob = aa.x*aa.x + aa.y*aa.y;
#pragma unroll
                    for (int w = 0; w < 10; ++w)
                        acc[w] += ((y >> w) & 1) ? -prob : prob;
                }
            }
#pragma unroll
            for (int w = 0; w < 10; ++w) {
                float v = acc[w];
                v += __shfl_xor_sync(0xffffffffu, v, 16);
                v += __shfl_xor_sync(0xffffffffu, v, 8);
                v += __shfl_xor_sync(0xffffffffu, v, 4);
                v += __shfl_xor_sync(0xffffffffu, v, 2);
                v += __shfl_xor_sync(0xffffffffu, v, 1);
                if ((tid & 31) == 0) atomicAdd(&qexp[c][w], v);
            }
            __syncthreads();
        }

        // ---- LSTM cell update ----
        if (tid < HH) {
            int h = tid;
            float fg = 1.f / (1.f + expf(-qexp[0][h]));
            float ig = 1.f / (1.f + expf(-qexp[1][h]));
            float gg = tanhf(qexp[2][h]);
            float og = 1.f / (1.f + expf(-qexp[3][h]));
            float cn = fg * scx[h] + ig * gg;
            float hn = og * tanhf(cn);
            scx[h] = cn; shx[h] = hn;
            out[((size_t)(t*BB) + b)*HH + h] = hn;
        }
        __syncthreads();
    }

    if (tid < HH) {
        out[(size_t)TT*BB*HH + (size_t)b*HH + tid]            = shx[tid];
        out[(size_t)TT*BB*HH + (size_t)BB*HH + (size_t)b*HH + tid] = scx[tid];
    }
}

extern "C" void kernel_launch(void* const* d_in, const int* in_sizes, int n_in,
                              void* d_out, int out_size) {
    (void)in_sizes; (void)n_in; (void)out_size;
    const float* inputs  = (const float*)d_in[0];
    const float* qparams = (const float*)d_in[1];
    const float* Wf = (const float*)d_in[2];
    const float* bf = (const float*)d_in[3];
    const float* Wi = (const float*)d_in[4];
    const float* bi = (const float*)d_in[5];
    const float* Wg = (const float*)d_in[6];
    const float* bg = (const float*)d_in[7];
    const float* Wo = (const float*)d_in[8];
    const float* bo = (const float*)d_in[9];
    float* out = (float*)d_out;
    qlstm_kernel<<<BB, NTH>>>(inputs, qparams, Wf, bf, Wi, bi, Wg, bg, Wo, bo, out);
}

// round 2
// speedup vs baseline: 1.5273x; 1.5273x over previous
#include <cuda_runtime.h>

// QLSTM on GB300. One CTA per batch element, T=64 recurrence in-kernel.
// 4 circuits/CTA, 64 threads each (16 amps/thread -> 4 gates per smem pass).
// 6 passes/circuit/step: init+w0-3 | w4-7 | w8-9+ring | L2 w0-3 | L2 w4-7 |
// L2 w8-9 + expectations (L2 ring folded into parity masks).
// Double-buffered statevectors (1 barrier/pass), per-circuit named barriers.

#define TT 64
#define BB 256
#define DD 32
#define HH 10
#define NTH 256

struct Smem {
    float2 sv0[4][1024];
    float2 sv1[4][1024];
    float  sW[4][HH][42];
    float  sBias[4][HH];
    float4 sU[2][HH];
    float  enc_c[4][HH];
    float  enc_s[4][HH];
    float  qpart[4][2][HH];
    float  comb_x[DD];
    float  comb_h[HH];
};

__device__ __forceinline__ void su2(float2 &a0, float2 &a1,
                                    float ax, float ay, float bx, float by) {
    float n0x = ax*a0.x - ay*a0.y - bx*a1.x - by*a1.y;
    float n0y = ax*a0.y + ay*a0.x - bx*a1.y + by*a1.x;
    float n1x = bx*a0.x - by*a0.y + ax*a1.x + ay*a1.y;
    float n1y = bx*a0.y + by*a0.x + ax*a1.y - ay*a1.x;
    a0.x = n0x; a0.y = n0y; a1.x = n1x; a1.y = n1y;
}

// Ring CNOT chain: y_w = x0^..^xw (w>=1), y_0 = x1^..^x9.
__device__ __forceinline__ int ring_map(int x) {
    int pref = x;
    pref ^= pref << 1;
    pref ^= pref << 2;
    pref ^= pref << 4;
    pref ^= pref << 8;
    return (pref & 0x3FE) | (((pref >> 9) ^ x) & 1);
}

// smem address of amp p under XOR swizzle
__device__ __forceinline__ int swz(int p) { return p ^ ((p >> 4) & 15); }

// per-circuit named barrier (64 threads = 2 warps)
__device__ __forceinline__ void cbar(int c) {
    asm volatile("bar.sync %0, 64;" :: "r"(c + 1) : "memory");
}

// apply 4 gates on register bits 0..3 of the 16-amp tile
__device__ __forceinline__ void gates4(float2 a[16], const float4* __restrict__ U) {
#pragma unroll
    for (int bit = 0; bit < 4; ++bit) {
        float4 u = U[bit];
        int m1 = 1 << bit;
#pragma unroll
        for (int m = 0; m < 16; ++m)
            if (!(m & m1))
                su2(a[m], a[m | m1], u.x, u.y, u.z, u.w);
    }
}

__device__ __forceinline__ void read16(const float2* __restrict__ src, int q, float2 a[16]) {
    int rb = q << 4, rs = q & 15;
#pragma unroll
    for (int j = 0; j < 16; ++j) a[j] = src[rb | (j ^ rs)];
}

// write rotated-right-by-4 (k -> k+4), swizzled
__device__ __forceinline__ void write_rot4(float2* __restrict__ dst, int q, const float2 a[16]) {
    int lo = (q & 15) ^ (q >> 4);
    int hi = q & 0x30;
#pragma unroll
    for (int j = 0; j < 16; ++j)
        dst[hi | (j << 6) | (lo ^ ((j & 3) << 2))] = a[j];
}

__global__ void __launch_bounds__(NTH, 2)
qlstm_kernel(const float* __restrict__ inputs,  // [T,B,D]
             const float* __restrict__ qparams, // [2,10,3]
             const float* __restrict__ Wf, const float* __restrict__ bf,
             const float* __restrict__ Wi, const float* __restrict__ bi,
             const float* __restrict__ Wg, const float* __restrict__ bg,
             const float* __restrict__ Wo, const float* __restrict__ bo,
             float* __restrict__ out)
{
    extern __shared__ char smem_raw[];
    Smem* S = (Smem*)smem_raw;

    const int tid = threadIdx.x;
    const int b   = blockIdx.x;
    const int c   = tid >> 6;         // circuit 0..3 (2 warps each)
    const int q   = tid & 63;         // 16-amp tile index (phys bits 4..9)
    float2* bufX = S->sv0[c];
    float2* bufY = S->sv1[c];

    // ---- one-time setup ----
    for (int i = tid; i < 420; i += NTH) {
        ((float*)S->sW)[i]        = Wf[i];
        ((float*)S->sW)[420 + i]  = Wi[i];
        ((float*)S->sW)[840 + i]  = Wg[i];
        ((float*)S->sW)[1260 + i] = Wo[i];
    }
    if (tid < HH) {
        S->sBias[0][tid] = bf[tid]; S->sBias[1][tid] = bi[tid];
        S->sBias[2][tid] = bg[tid]; S->sBias[3][tid] = bo[tid];
        S->comb_h[tid] = 0.f;
    }
    if (tid < 20) {
        int l = tid / 10, w = tid % 10;
        float tz = qparams[(l*10 + w)*3 + 0];
        float tx = qparams[(l*10 + w)*3 + 1];
        float ty = qparams[(l*10 + w)*3 + 2];
        float c1, s1, c2, s2, c3, s3;
        sincosf(0.5f*tz, &s1, &c1);
        sincosf(0.5f*tx, &s2, &c2);
        sincosf(0.5f*ty, &s3, &c3);
        float aAx =  c2*c1, aAy = -c2*s1;   // RX*RZ
        float bAx = -s2*s1, bAy = -s2*c1;
        S->sU[l][w] = make_float4(c3*aAx - s3*bAx, c3*aAy - s3*bAy,
                                  s3*aAx + c3*bAx, s3*aAy + c3*bAy);
    }
    float cx_reg = 0.f, hx_reg = 0.f;
    __syncthreads();

    for (int t = 0; t < TT; ++t) {
        // ---- load x, then CTA sync (also publishes comb_h from prev LSTM) ----
        if (tid < DD) S->comb_x[tid] = inputs[((size_t)(t*BB) + b)*DD + tid];
        __syncthreads();

        // ---- per-circuit pre-activation + encoding angles ----
        if (q < HH) {
            const float* wr = S->sW[c][q];
            float acc0 = S->sBias[c][q], acc1 = 0.f;
#pragma unroll
            for (int j = 0; j < DD; j += 2) {
                acc0 = fmaf(wr[j],   S->comb_x[j],   acc0);
                acc1 = fmaf(wr[j+1], S->comb_x[j+1], acc1);
            }
#pragma unroll
            for (int j = 0; j < HH; j += 2) {
                acc0 = fmaf(wr[DD+j],   S->comb_h[j],   acc0);
                acc1 = fmaf(wr[DD+j+1], S->comb_h[j+1], acc1);
            }
            float cc, ss;
            sincosf(0.5f*(acc0 + acc1), &ss, &cc);
            S->enc_c[c][q] = cc; S->enc_s[c][q] = ss;
        }
        cbar(c);

        // ---- P1: init product state + L1 wires 0-3, write k=0 -> k=4 ----
        {
            float fq = 1.f;
#pragma unroll
            for (int w = 0; w < 6; ++w)
                fq *= ((q >> w) & 1) ? S->enc_s[c][4 + w] : S->enc_c[c][4 + w];
            float c0 = S->enc_c[c][0], s0 = S->enc_s[c][0];
            float c1 = S->enc_c[c][1], s1 = S->enc_s[c][1];
            float c2 = S->enc_c[c][2], s2 = S->enc_s[c][2];
            float c3 = S->enc_c[c][3], s3 = S->enc_s[c][3];
            float2 a[16];
#pragma unroll
            for (int j = 0; j < 16; ++j) {
                float v = fq * ((j & 1) ? s0 : c0) * ((j & 2) ? s1 : c1)
                             * ((j & 4) ? s2 : c2) * ((j & 8) ? s3 : c3);
                a[j] = make_float2(v, 0.f);
            }
            gates4(a, &S->sU[0][0]);
            write_rot4(bufX, q, a);
            cbar(c);
        }
        // ---- P2: L1 wires 4-7 (k=4 -> k=8) ----
        {
            float2 a[16];
            read16(bufX, q, a);
            gates4(a, &S->sU[0][4]);
            write_rot4(bufY, q, a);
            cbar(c);
        }
        // ---- P3: L1 wires 8,9 + ring permutation (k=8 -> k=0) ----
        {
            float2 a[16];
            read16(bufY, q, a);
            float4 u8 = S->sU[0][8], u9 = S->sU[0][9];
#pragma unroll
            for (int m = 0; m < 16; m += 2) su2(a[m], a[m+1], u8.x,u8.y,u8.z,u8.w);
#pragma unroll
            for (int m = 0; m < 16; ++m)
                if (!(m & 2)) su2(a[m], a[m | 2], u9.x,u9.y,u9.z,u9.w);
            int rb = q << 4;
#pragma unroll
            for (int j = 0; j < 16; ++j) {
                int p = rb | j;
                int x = ((p >> 2) | (p << 8)) & 1023;  // logical index at k=8
                int y = ring_map(x);
                bufX[swz(y)] = a[j];
            }
            cbar(c);
        }
        // ---- P4: L2 wires 0-3 (k=0 -> k=4) ----
        {
            float2 a[16];
            read16(bufX, q, a);
            gates4(a, &S->sU[1][0]);
            write_rot4(bufY, q, a);
            cbar(c);
        }
        // ---- P5: L2 wires 4-7 (k=4 -> k=8) ----
        {
            float2 a[16];
            read16(bufY, q, a);
            gates4(a, &S->sU[1][4]);
            write_rot4(bufX, q, a);
            cbar(c);
        }
        // ---- P6: L2 wires 8,9 + expectations (ring folded into parities) ----
        {
            float2 a[16];
            read16(bufX, q, a);
            float4 u8 = S->sU[1][8], u9 = S->sU[1][9];
#pragma unroll
            for (int m = 0; m < 16; m += 2) su2(a[m], a[m+1], u8.x,u8.y,u8.z,u8.w);
#pragma unroll
            for (int m = 0; m < 16; ++m)
                if (!(m & 2)) su2(a[m], a[m | 2], u9.x,u9.y,u9.z,u9.w);
            float acc[10];
#pragma unroll
            for (int w = 0; w < 10; ++w) acc[w] = 0.f;
            int rb = q << 4;
#pragma unroll
            for (int j = 0; j < 16; ++j) {
                int p = rb | j;
                int x = ((p >> 2) | (p << 8)) & 1023;
                unsigned y = (unsigned)ring_map(x);
                float prob = fmaf(a[j].x, a[j].x, a[j].y * a[j].y);
                unsigned pb = __float_as_uint(prob);
#pragma unroll
                for (int w = 0; w < 10; ++w)
                    acc[w] += __uint_as_float(pb ^ ((y << (31 - w)) & 0x80000000u));
            }
#pragma unroll
            for (int w = 0; w < 10; ++w) {
                float v = acc[w];
                v += __shfl_xor_sync(0xffffffffu, v, 16);
                v += __shfl_xor_sync(0xffffffffu, v, 8);
                v += __shfl_xor_sync(0xffffffffu, v, 4);
                v += __shfl_xor_sync(0xffffffffu, v, 2);
                v += __shfl_xor_sync(0xffffffffu, v, 1);
                if ((q & 31) == 0) S->qpart[c][q >> 5][w] = v;
            }
        }
        __syncthreads();

        // ---- LSTM cell update (threads 0..9) ----
        if (tid < HH) {
            int h = tid;
            float qf = S->qpart[0][0][h] + S->qpart[0][1][h];
            float qi = S->qpart[1][0][h] + S->qpart[1][1][h];
            float qg = S->qpart[2][0][h] + S->qpart[2][1][h];
            float qo = S->qpart[3][0][h] + S->qpart[3][1][h];
            float fg = 1.f / (1.f + expf(-qf));
            float ig = 1.f / (1.f + expf(-qi));
            float gg = tanhf(qg);
            float og = 1.f / (1.f + expf(-qo));
            cx_reg = fg * cx_reg + ig * gg;
            hx_reg = og * tanhf(cx_reg);
            S->comb_h[h] = hx_reg;
            out[((size_t)(t*BB) + b)*HH + h] = hx_reg;
        }
    }

    if (tid < HH) {
        out[(size_t)TT*BB*HH + (size_t)b*HH + tid]                       = hx_reg;
        out[(size_t)TT*BB*HH + (size_t)BB*HH + (size_t)b*HH + tid]       = cx_reg;
    }
}

extern "C" void kernel_launch(void* const* d_in, const int* in_sizes, int n_in,
                              void* d_out, int out_size) {
    (void)in_sizes; (void)n_in; (void)out_size;
    const float* inputs  = (const float*)d_in[0];
    const float* qparams = (const float*)d_in[1];
    const float* Wf = (const float*)d_in[2];
    const float* bf = (const float*)d_in[3];
    const float* Wi = (const float*)d_in[4];
    const float* bi = (const float*)d_in[5];
    const float* Wg = (const float*)d_in[6];
    const float* bg = (const float*)d_in[7];
    const float* Wo = (const float*)d_in[8];
    const float* bo = (const float*)d_in[9];
    float* out = (float*)d_out;
    cudaFuncSetAttribute(qlstm_kernel,
                         cudaFuncAttributeMaxDynamicSharedMemorySize,
                         (int)sizeof(Smem));
    qlstm_kernel<<<BB, NTH, sizeof(Smem)>>>(inputs, qparams, Wf, bf, Wi, bi,
                                            Wg, bg, Wo, bo, out);
}

// round 3
// speedup vs baseline: 2.7165x; 1.7786x over previous
#include <cuda_runtime.h>

// QLSTM on GB300. One CTA/batch element, T=64 recurrence in-kernel.
// 4 circuits x 64 threads (16 amps/thread). Per step per circuit:
//   pre-act -> per-wire vectors (L1 rotations folded into product state)
//   PA: write product state directly into L1-ring-permuted layout (1 pass)
//   P4: L2 wires 0-3 | P5: L2 wires 4-7 (packed f32x2 su2 gates)
//   P6: L2 wires 8-9 + Walsh-transform expectations (L2 ring = parity masks)

#define TT 64
#define BB 256
#define DD 32
#define HH 10
#define NTH 256

typedef unsigned long long u64;
typedef unsigned short u16;

struct Smem {
    u64   sv0[4][1024];          // 32 KB
    u64   sv1[4][1024];          // 32 KB
    u64   sUc[HH][6];            // layer-2 packed su2 consts
    float4 sU0[HH];              // layer-1 raw (ax,ay,bx,by)
    u64   venc[4][HH][2];        // per-wire 2-vectors (enc+L1 rot)
    u64   Ttab[4][16];           // low-wire product table
    u16   swa[1024];             // x -> swz(ring_map(x)) element offsets
    float sW[4][HH][42];
    float sBias[4][HH];
    float qpart[2][4][2][9];     // [step parity][circuit][warp][slot]
    float comb_x[2][DD];
    float comb_h[4][HH];
};

__device__ __forceinline__ u64 f2fma(u64 a, u64 b, u64 c) {
    u64 d;
    asm("fma.rn.f32x2 %0, %1, %2, %3;" : "=l"(d) : "l"(a), "l"(b), "l"(c));
    return d;
}
__device__ __forceinline__ u64 f2mul(u64 a, u64 b) {
    u64 d;
    asm("mul.rn.f32x2 %0, %1, %2;" : "=l"(d) : "l"(a), "l"(b));
    return d;
}
__device__ __forceinline__ u64 dswp(u64 a) {
    u64 r;
    asm("{\n\t.reg .b32 l, h;\n\tmov.b64 {l, h}, %1;\n\tmov.b64 %0, {h, l};\n\t}"
        : "=l"(r) : "l"(a));
    return r;
}
__device__ __forceinline__ u64 pk(float lo, float hi) {
    return (u64)__float_as_uint(lo) | ((u64)__float_as_uint(hi) << 32);
}
__device__ __forceinline__ float ulo(u64 v) { return __uint_as_float((unsigned)v); }
__device__ __forceinline__ float uhi(u64 v) { return __uint_as_float((unsigned)(v >> 32)); }

// Ring CNOT chain: y_w = x0^..^xw (w>=1), y_0 = x1^..^x9.
__device__ __forceinline__ int ring_map(int x) {
    int p = x;
    p ^= p << 1; p ^= p << 2; p ^= p << 4; p ^= p << 8;
    return (p & 0x3FE) | (((p >> 9) ^ x) & 1);
}
__device__ __forceinline__ int swz(int p) { return p ^ ((p >> 4) & 15); }

__device__ __forceinline__ void cbar(int c) {
    asm volatile("bar.sync %0, 64;" :: "r"(c + 1) : "memory");
}

// packed su2 on register bit B across the 16-amp tile
template<int B>
__device__ __forceinline__ void apply_bit(u64 a[16], const u64* __restrict__ C) {
    u64 c0 = C[0], c1 = C[1], c2 = C[2], c3 = C[3], c4 = C[4], c5 = C[5];
#pragma unroll
    for (int m = 0; m < 16; ++m) {
        if (m & (1 << B)) continue;
        const int m1 = m | (1 << B);
        u64 s0 = dswp(a[m]), s1 = dswp(a[m1]);
        u64 n0 = f2mul(c3, s1);
        n0 = f2fma(c2, a[m1], n0);
        n0 = f2fma(c1, s0, n0);
        n0 = f2fma(c0, a[m], n0);
        u64 n1 = f2mul(c5, s1);
        n1 = f2fma(c0, a[m1], n1);
        n1 = f2fma(c3, s0, n1);
        n1 = f2fma(c4, a[m], n1);
        a[m] = n0; a[m1] = n1;
    }
}

__device__ __forceinline__ void read16u(const u64* __restrict__ src, int q, u64 a[16]) {
    const int rb = q << 4, rs = q & 15;
#pragma unroll
    for (int j = 0; j < 16; ++j) a[j] = src[rb | (j ^ rs)];
}

// write rotated-right-by-4 (k -> k+4), swizzled
__device__ __forceinline__ void write_rot4u(u64* __restrict__ dst, int q, const u64 a[16]) {
    const int lo = (q & 15) ^ (q >> 4);
    const int hi = q & 0x30;
#pragma unroll
    for (int j = 0; j < 16; ++j)
        dst[hi | (j << 6) | (lo ^ ((j & 3) << 2))] = a[j];
}

// 5-stage signed Walsh butterfly over the 32 lanes
__device__ __forceinline__ float wht5(float v, int lane) {
#pragma unroll
    for (int i = 0; i < 5; ++i) {
        float t = __shfl_xor_sync(0xffffffffu, v, 1 << i);
        v = (lane & (1 << i)) ? (t - v) : (v + t);
    }
    return v;
}

__global__ void __launch_bounds__(NTH, 2)
qlstm_kernel(const float* __restrict__ inputs,
             const float* __restrict__ qparams,
             const float* __restrict__ Wf, const float* __restrict__ bf,
             const float* __restrict__ Wi, const float* __restrict__ bi,
             const float* __restrict__ Wg, const float* __restrict__ bg,
             const float* __restrict__ Wo, const float* __restrict__ bo,
             float* __restrict__ out)
{
    extern __shared__ char smem_raw[];
    Smem* S = (Smem*)smem_raw;

    const int tid = threadIdx.x;
    const int b   = blockIdx.x;
    const int c   = tid >> 6;      // circuit 0..3 (2 warps each)
    const int q   = tid & 63;      // 16-amp tile index (phys bits 4..9)
    const int lane = q & 31;
    u64* bufX = S->sv0[c];
    u64* bufY = S->sv1[c];

    // ---- one-time setup ----
    for (int i = tid; i < 420; i += NTH) {
        ((float*)S->sW)[i]        = Wf[i];
        ((float*)S->sW)[420 + i]  = Wi[i];
        ((float*)S->sW)[840 + i]  = Wg[i];
        ((float*)S->sW)[1260 + i] = Wo[i];
    }
    for (int i = tid; i < 1024; i += NTH)
        S->swa[i] = (u16)swz(ring_map(i));
    if (tid < HH) {
        S->sBias[0][tid] = bf[tid]; S->sBias[1][tid] = bi[tid];
        S->sBias[2][tid] = bg[tid]; S->sBias[3][tid] = bo[tid];
    }
    if (q < HH) S->comb_h[c][q] = 0.f;
    if (tid < 20) {
        int l = tid / 10, w = tid % 10;
        float tz = qparams[(l*10 + w)*3 + 0];
        float tx = qparams[(l*10 + w)*3 + 1];
        float ty = qparams[(l*10 + w)*3 + 2];
        float c1, s1, c2, s2, c3, s3;
        sincosf(0.5f*tz, &s1, &c1);
        sincosf(0.5f*tx, &s2, &c2);
        sincosf(0.5f*ty, &s3, &c3);
        float aAx =  c2*c1, aAy = -c2*s1;   // RX*RZ
        float bAx = -s2*s1, bAy = -s2*c1;
        float ax = c3*aAx - s3*bAx, ay = c3*aAy - s3*bAy;   // U = RY*RX*RZ
        float bx = s3*aAx + c3*bAx, by = s3*aAy + c3*bAy;
        if (l == 0) {
            S->sU0[w] = make_float4(ax, ay, bx, by);
        } else {
            S->sUc[w][0] = pk( ax,  ax);
            S->sUc[w][1] = pk(-ay,  ay);
            S->sUc[w][2] = pk(-bx, -bx);
            S->sUc[w][3] = pk(-by,  by);
            S->sUc[w][4] = pk( bx,  bx);
            S->sUc[w][5] = pk( ay, -ay);
        }
    }
    if (tid < DD) S->comb_x[0][tid] = inputs[(size_t)b*DD + tid];
    float cx_reg = 0.f, hx_reg = 0.f;
    __syncthreads();

    for (int t = 0; t < TT; ++t) {
        const int par = t & 1;
        // prefetch next step's x early (hide LDG latency)
        float xpre = 0.f;
        const bool pf = (tid < DD) && (t + 1 < TT);
        if (pf) xpre = inputs[((size_t)((t+1)*BB) + b)*DD + tid];

        // ---- pre-activation -> encoding + L1 rotation folded per-wire vectors
        if (q < HH) {
            const float* wr = S->sW[c][q];
            float acc0 = S->sBias[c][q], acc1 = 0.f;
#pragma unroll
            for (int j = 0; j < DD; j += 2) {
                acc0 = fmaf(wr[j],   S->comb_x[par][j],   acc0);
                acc1 = fmaf(wr[j+1], S->comb_x[par][j+1], acc1);
            }
#pragma unroll
            for (int j = 0; j < HH; j += 2) {
                acc0 = fmaf(wr[DD+j],   S->comb_h[c][j],   acc0);
                acc1 = fmaf(wr[DD+j+1], S->comb_h[c][j+1], acc1);
            }
            float cc, ss;
            sincosf(0.5f*(acc0 + acc1), &ss, &cc);
            float4 U = S->sU0[q];
            // v = U * (cc, ss)^T   (complex 2-vector)
            S->venc[c][q][0] = pk(U.x*cc - U.z*ss, U.y*cc + U.w*ss);
            S->venc[c][q][1] = pk(U.z*cc + U.x*ss, U.w*cc - U.y*ss);
        }
        __syncwarp();
        if (q < 16) {   // low-wire (0..3) product table
            u64 t0 = S->venc[c][0][q & 1];
            float tr = ulo(t0), ti = uhi(t0);
#pragma unroll
            for (int w = 1; w < 4; ++w) {
                u64 tv = S->venc[c][w][(q >> w) & 1];
                float br = ulo(tv), bi = uhi(tv);
                float nr = tr*br - ti*bi;
                ti = tr*bi + ti*br; tr = nr;
            }
            S->Ttab[c][q] = pk(tr, ti);
        }
        cbar(c);

        // ---- PA: write product state into L1-ring-permuted layout ----
        {
            u64 p0 = S->venc[c][4][q & 1];
            float pr = ulo(p0), pi = uhi(p0);
#pragma unroll
            for (int i = 1; i < 6; ++i) {
                u64 tv = S->venc[c][4 + i][(q >> i) & 1];
                float br = ulo(tv), bi = uhi(tv);
                float nr = pr*br - pi*bi;
                pi = pr*bi + pi*br; pr = nr;
            }
            const uint4* tp = (const uint4*)(S->swa + (q << 4));
            uint4 o0 = tp[0], o1 = tp[1];
            unsigned oo[8] = {o0.x, o0.y, o0.z, o0.w, o1.x, o1.y, o1.z, o1.w};
            float2* dst = (float2*)bufX;
#pragma unroll
            for (int j = 0; j < 16; ++j) {
                u64 tv = S->Ttab[c][j];
                float br = ulo(tv), bi = uhi(tv);
                float ar = pr*br - pi*bi;
                float ai = pr*bi + pi*br;
                unsigned off = (j & 1) ? (oo[j >> 1] >> 16) : (oo[j >> 1] & 0xFFFFu);
                dst[off] = make_float2(ar, ai);
            }
            cbar(c);
        }
        // ---- P4: L2 wires 0-3 (k=0 -> k=4) ----
        {
            u64 a[16];
            read16u(bufX, q, a);
            apply_bit<0>(a, S->sUc[0]);
            apply_bit<1>(a, S->sUc[1]);
            apply_bit<2>(a, S->sUc[2]);
            apply_bit<3>(a, S->sUc[3]);
            write_rot4u(bufY, q, a);
            cbar(c);
        }
        // ---- P5: L2 wires 4-7 (k=4 -> k=8) ----
        {
            u64 a[16];
            read16u(bufY, q, a);
            apply_bit<0>(a, S->sUc[4]);
            apply_bit<1>(a, S->sUc[5]);
            apply_bit<2>(a, S->sUc[6]);
            apply_bit<3>(a, S->sUc[7]);
            write_rot4u(bufX, q, a);
            cbar(c);
        }
        // ---- P6: L2 wires 8,9 + Walsh expectations ----
        {
            u64 a[16];
            read16u(bufX, q, a);
            apply_bit<0>(a, S->sUc[8]);
            apply_bit<1>(a, S->sUc[9]);
            float p[16];
#pragma unroll
            for (int j = 0; j < 16; ++j) {
                float x = ulo(a[j]), y = uhi(a[j]);
                p[j] = fmaf(x, x, y * y);
            }
            float s[8], d[8];
#pragma unroll
            for (int k = 0; k < 8; ++k) {
                s[k] = p[2*k] + p[2*k+1];
                d[k] = p[2*k] - p[2*k+1];
            }
            float S12 = (s[0]+s[1]) - (s[2]+s[3]) - (s[4]+s[5]) + (s[6]+s[7]);
            float S11 = d[0]-d[1]+d[2]-d[3]-d[4]+d[5]-d[6]+d[7];
            float S13 = d[0]+d[1]-d[2]-d[3]-d[4]-d[5]+d[6]+d[7];
            float S15 = d[0]-d[1]-d[2]+d[3]-d[4]+d[5]+d[6]-d[7];
            float W12 = wht5(S12, lane);
            float W11 = wht5(S11, lane);
            float W13 = wht5(S13, lane);
            float W15 = wht5(S15, lane);
            const int wci = q >> 5;
            float* qp = S->qpart[par][c][wci];
            if (lane == 0)        qp[1] = W12;
            else if (lane == 1)   qp[2] = W12;
            else if (lane == 3)   qp[3] = W12;
            else if (lane == 7)   qp[4] = W12;
            else if (lane == 15)  qp[5] = W12;
            else if (lane == 31) {
                qp[0] = W11; qp[6] = W12; qp[7] = W13; qp[8] = W15;
            }
        }
        if (pf) S->comb_x[(t + 1) & 1][tid] = xpre;
        __syncthreads();

        // ---- LSTM cell update (per-circuit redundant, threads q<10) ----
        if (q < HH) {
            const int h = q;
            const int slot = (h < 7) ? h : h - 1;
            const float sg = (h >= 1 && h <= 6) ? 1.f : -1.f;
            float qv[4];
#pragma unroll
            for (int g = 0; g < 4; ++g)
                qv[g] = S->qpart[par][g][0][slot] + sg * S->qpart[par][g][1][slot];
            float fg = 1.f / (1.f + expf(-qv[0]));
            float ig = 1.f / (1.f + expf(-qv[1]));
            float gg = tanhf(qv[2]);
            float og = 1.f / (1.f + expf(-qv[3]));
            cx_reg = fg * cx_reg + ig * gg;
            hx_reg = og * tanhf(cx_reg);
            S->comb_h[c][h] = hx_reg;
            if (c == 0)
                out[((size_t)(t*BB) + b)*HH + h] = hx_reg;
        }
        __syncwarp();
    }

    if (tid < HH) {
        out[(size_t)TT*BB*HH + (size_t)b*HH + tid]                 = hx_reg;
        out[(size_t)TT*BB*HH + (size_t)BB*HH + (size_t)b*HH + tid] = cx_reg;
    }
}

extern "C" void kernel_launch(void* const* d_in, const int* in_sizes, int n_in,
                              void* d_out, int out_size) {
    (void)in_sizes; (void)n_in; (void)out_size;
    const float* inputs  = (const float*)d_in[0];
    const float* qparams = (const float*)d_in[1];
    const float* Wf = (const float*)d_in[2];
    const float* bf = (const float*)d_in[3];
    const float* Wi = (const float*)d_in[4];
    const float* bi = (const float*)d_in[5];
    const float* Wg = (const float*)d_in[6];
    const float* bg = (const float*)d_in[7];
    const float* Wo = (const float*)d_in[8];
    const float* bo = (const float*)d_in[9];
    float* out = (float*)d_out;
    cudaFuncSetAttribute(qlstm_kernel,
                         cudaFuncAttributeMaxDynamicSharedMemorySize,
                         (int)sizeof(Smem));
    qlstm_kernel<<<BB, NTH, sizeof(Smem)>>>(inputs, qparams, Wf, bf, Wi, bi,
                                            Wg, bg, Wo, bo, out);
}

// round 4
// speedup vs baseline: 3.0357x; 1.1175x over previous
#include <cuda_runtime.h>

// QLSTM on GB300. One CTA/batch element, T=64 recurrence in-kernel.
// 4 circuits/CTA, ONE WARP per circuit, 32 amps/thread (5 register bits).
// Per step/circuit: PA write (product state with L1 rotations + L1 CNOT ring
// folded in) -> P4 (L2 wires 0-4) -> P5 (L2 wires 5-9 + Walsh expectations,
// L2 ring folded into parity masks). All intra-circuit sync = __syncwarp();
// one __syncthreads per step for the LSTM gate exchange.

#define TT 64
#define BB 256
#define DD 32
#define HH 10
#define NTH 128

typedef unsigned long long u64;

struct Smem {
    u64    sv[4][1024];          // 32 KB, single buffer per circuit
    u64    sUc[HH][6];           // layer-2 packed su2 consts
    float4 sU0[HH];              // layer-1 (ax,ay,bx,by)
    u64    venc[4][HH][2];       // per-wire 2-vectors (enc + L1 rot)
    u64    Ttab[4][32];          // low-wire (0-4) product table
    float  sW[4][HH][42];
    float  sBias[4][HH];
    float  qpart[2][4][HH];      // [parity][circuit][wire]
    float  comb_x[2][DD];
};

__device__ __forceinline__ u64 f2fma(u64 a, u64 b, u64 c) {
    u64 d;
    asm("fma.rn.f32x2 %0, %1, %2, %3;" : "=l"(d) : "l"(a), "l"(b), "l"(c));
    return d;
}
__device__ __forceinline__ u64 f2mul(u64 a, u64 b) {
    u64 d;
    asm("mul.rn.f32x2 %0, %1, %2;" : "=l"(d) : "l"(a), "l"(b));
    return d;
}
__device__ __forceinline__ u64 dswp(u64 a) {
    u64 r;
    asm("{\n\t.reg .b32 l, h;\n\tmov.b64 {l, h}, %1;\n\tmov.b64 %0, {h, l};\n\t}"
        : "=l"(r) : "l"(a));
    return r;
}
__device__ __forceinline__ u64 pk(float lo, float hi) {
    return (u64)__float_as_uint(lo) | ((u64)__float_as_uint(hi) << 32);
}
__device__ __forceinline__ float ulo(u64 v) { return __uint_as_float((unsigned)v); }
__device__ __forceinline__ float uhi(u64 v) { return __uint_as_float((unsigned)(v >> 32)); }

// Ring CNOT chain (GF2-linear): y_w = x0^..^xw (w>=1), y_0 = x1^..^x9.
__host__ __device__ constexpr int ring_c(int x) {
    int p = x;
    p ^= p << 1; p ^= p << 2; p ^= p << 4; p ^= p << 8;
    return (p & 0x3FE) | (((p >> 9) ^ x) & 1);
}
// storage address map (GF2-linear)
__host__ __device__ constexpr int A_c(int p) { return p ^ ((p >> 5) & 31); }

// packed su2 on register bit B across the 32-amp tile
template<int B>
__device__ __forceinline__ void apply_bit(u64 a[32], const u64* __restrict__ C) {
    u64 c0 = C[0], c1 = C[1], c2 = C[2], c3 = C[3], c4 = C[4], c5 = C[5];
#pragma unroll
    for (int m = 0; m < 32; ++m) {
        if (m & (1 << B)) continue;
        const int m1 = m | (1 << B);
        u64 s0 = dswp(a[m]), s1 = dswp(a[m1]);
        u64 n0 = f2mul(c3, s1);
        n0 = f2fma(c2, a[m1], n0);
        n0 = f2fma(c1, s0, n0);
        n0 = f2fma(c0, a[m], n0);
        u64 n1 = f2mul(c5, s1);
        n1 = f2fma(c0, a[m1], n1);
        n1 = f2fma(c3, s0, n1);
        n1 = f2fma(c4, a[m], n1);
        a[m] = n0; a[m1] = n1;
    }
}

// 5-stage signed Walsh butterfly over 32 lanes; W[lane]=sum_l v[l](-1)^pop(l&lane)
__device__ __forceinline__ float wht5(float v, int lane) {
#pragma unroll
    for (int i = 0; i < 5; ++i) {
        float t = __shfl_xor_sync(0xffffffffu, v, 1 << i);
        v = (lane & (1 << i)) ? (t - v) : (v + t);
    }
    return v;
}

__global__ void __launch_bounds__(NTH, 2)
qlstm_kernel(const float* __restrict__ inputs,
             const float* __restrict__ qparams,
             const float* __restrict__ Wf, const float* __restrict__ bf,
             const float* __restrict__ Wi, const float* __restrict__ bi,
             const float* __restrict__ Wg, const float* __restrict__ bg,
             const float* __restrict__ Wo, const float* __restrict__ bo,
             float* __restrict__ out)
{
    extern __shared__ char smem_raw[];
    Smem* S = (Smem*)smem_raw;

    const int tid  = threadIdx.x;
    const int b    = blockIdx.x;
    const int c    = tid >> 5;      // circuit 0..3 == warp id
    const int lane = tid & 31;      // amp tile index q (phys bits 5..9)
    const int q    = lane;
    u64* sv = S->sv[c];

    // ---- one-time setup ----
    for (int i = tid; i < 420; i += NTH) {
        ((float*)S->sW)[i]        = Wf[i];
        ((float*)S->sW)[420 + i]  = Wi[i];
        ((float*)S->sW)[840 + i]  = Wg[i];
        ((float*)S->sW)[1260 + i] = Wo[i];
    }
    if (tid < HH) {
        S->sBias[0][tid] = bf[tid]; S->sBias[1][tid] = bi[tid];
        S->sBias[2][tid] = bg[tid]; S->sBias[3][tid] = bo[tid];
    }
    if (tid < 20) {
        int l = tid / 10, w = tid % 10;
        float tz = qparams[(l*10 + w)*3 + 0];
        float tx = qparams[(l*10 + w)*3 + 1];
        float ty = qparams[(l*10 + w)*3 + 2];
        float c1, s1, c2, s2, c3, s3;
        sincosf(0.5f*tz, &s1, &c1);
        sincosf(0.5f*tx, &s2, &c2);
        sincosf(0.5f*ty, &s3, &c3);
        float aAx =  c2*c1, aAy = -c2*s1;   // RX*RZ
        float bAx = -s2*s1, bAy = -s2*c1;
        float ax = c3*aAx - s3*bAx, ay = c3*aAy - s3*bAy;   // U = RY*RX*RZ
        float bx = s3*aAx + c3*bAx, by = s3*aAy + c3*bAy;
        if (l == 0) {
            S->sU0[w] = make_float4(ax, ay, bx, by);
        } else {
            S->sUc[w][0] = pk( ax,  ax);
            S->sUc[w][1] = pk(-ay,  ay);
            S->sUc[w][2] = pk(-bx, -bx);
            S->sUc[w][3] = pk(-by,  by);
            S->sUc[w][4] = pk( bx,  bx);
            S->sUc[w][5] = pk( ay, -ay);
        }
    }
    if (tid < DD) S->comb_x[0][tid] = inputs[(size_t)b*DD + tid];
    const int cq = A_c(ring_c(q << 5));   // linear part of PA store address
    const int rbase = q * 33;             // read base: (q<<5)|q
    float cx_reg = 0.f, hx_reg = 0.f;
    __syncthreads();

    for (int t = 0; t < TT; ++t) {
        const int par = t & 1;
        float xpre = 0.f;
        const bool pf = (tid < DD) && (t + 1 < TT);
        if (pf) xpre = inputs[((size_t)((t+1)*BB) + b)*DD + tid];

        // ---- gather prev h via shfl (all lanes), pre-activation in lanes 0-9
        float hj[HH];
#pragma unroll
        for (int j = 0; j < HH; ++j)
            hj[j] = __shfl_sync(0xffffffffu, hx_reg, j);
        if (lane < HH) {
            const float* wr = S->sW[c][lane];
            float acc0 = S->sBias[c][lane], acc1 = 0.f;
#pragma unroll
            for (int j = 0; j < DD; j += 2) {
                acc0 = fmaf(wr[j],   S->comb_x[par][j],   acc0);
                acc1 = fmaf(wr[j+1], S->comb_x[par][j+1], acc1);
            }
#pragma unroll
            for (int j = 0; j < HH; j += 2) {
                acc0 = fmaf(wr[DD+j],   hj[j],   acc0);
                acc1 = fmaf(wr[DD+j+1], hj[j+1], acc1);
            }
            float cc, ss;
            sincosf(0.5f*(acc0 + acc1), &ss, &cc);
            float4 U = S->sU0[lane];
            S->venc[c][lane][0] = pk(U.x*cc - U.z*ss, U.y*cc + U.w*ss);
            S->venc[c][lane][1] = pk(U.z*cc + U.x*ss, U.w*cc - U.y*ss);
        }
        __syncwarp();

        // ---- low-wire (0-4) product table, one entry per lane ----
        {
            u64 t0 = S->venc[c][0][lane & 1];
            float tr = ulo(t0), ti = uhi(t0);
#pragma unroll
            for (int w = 1; w < 5; ++w) {
                u64 tv = S->venc[c][w][(lane >> w) & 1];
                float br = ulo(tv), bi = uhi(tv);
                float nr = tr*br - ti*bi;
                ti = tr*bi + ti*br; tr = nr;
            }
            S->Ttab[c][lane] = pk(tr, ti);
        }
        __syncwarp();

        // ---- PA: product state (L1 folded) into ring-permuted layout ----
        {
            u64 p0 = S->venc[c][5][q & 1];
            float pr = ulo(p0), pi = uhi(p0);
#pragma unroll
            for (int i = 1; i < 5; ++i) {
                u64 tv = S->venc[c][5 + i][(q >> i) & 1];
                float br = ulo(tv), bi = uhi(tv);
                float nr = pr*br - pi*bi;
                pi = pr*bi + pi*br; pr = nr;
            }
            u64 Prr = pk(pr, pr);
            u64 Pin = pk(-pi, pi);
#pragma unroll
            for (int j = 0; j < 32; ++j) {
                const int Kj = A_c(ring_c(j));     // compile-time constant
                u64 bv = S->Ttab[c][j];
                u64 n  = f2fma(Prr, bv, f2mul(Pin, dswp(bv)));
                sv[cq ^ Kj] = n;
            }
            __syncwarp();
        }

        // ---- P4: L2 wires 0-4 (k=0 -> k=5, same buffer) ----
        {
            u64 a[32];
#pragma unroll
            for (int j = 0; j < 32; ++j) a[j] = sv[rbase ^ j];
            apply_bit<0>(a, S->sUc[0]);
            apply_bit<1>(a, S->sUc[1]);
            apply_bit<2>(a, S->sUc[2]);
            apply_bit<3>(a, S->sUc[3]);
            apply_bit<4>(a, S->sUc[4]);
            __syncwarp();
#pragma unroll
            for (int j = 0; j < 32; ++j) sv[q ^ (33*j)] = a[j];
            __syncwarp();
        }

        // ---- P5: L2 wires 5-9 + Walsh expectations ----
        {
            u64 a[32];
#pragma unroll
            for (int j = 0; j < 32; ++j) a[j] = sv[rbase ^ j];
            apply_bit<0>(a, S->sUc[5]);
            apply_bit<1>(a, S->sUc[6]);
            apply_bit<2>(a, S->sUc[7]);
            apply_bit<3>(a, S->sUc[8]);
            apply_bit<4>(a, S->sUc[9]);

            float p[32];
#pragma unroll
            for (int j = 0; j < 32; ++j) {
                float x = ulo(a[j]), y = uhi(a[j]);
                p[j] = fmaf(x, x, y * y);
            }
            // register-side partial Walsh at prefix freqs {0,1,3,7,15,31}
            float s0[16], d0[16];
#pragma unroll
            for (int k = 0; k < 16; ++k) {
                s0[k] = p[2*k] + p[2*k+1];
                d0[k] = p[2*k] - p[2*k+1];
            }
            float Sh0 = ((s0[0]+s0[1])+(s0[2]+s0[3])) + ((s0[4]+s0[5])+(s0[6]+s0[7]))
                      + ((s0[8]+s0[9])+(s0[10]+s0[11])) + ((s0[12]+s0[13])+(s0[14]+s0[15]));
            float s1[8], d1[8];
#pragma unroll
            for (int k = 0; k < 8; ++k) {
                s1[k] = d0[2*k] + d0[2*k+1];
                d1[k] = d0[2*k] - d0[2*k+1];
            }
            float Sh1 = ((s1[0]+s1[1])+(s1[2]+s1[3])) + ((s1[4]+s1[5])+(s1[6]+s1[7]));
            float s2[4], d2[4];
#pragma unroll
            for (int k = 0; k < 4; ++k) {
                s2[k] = d1[2*k] + d1[2*k+1];
                d2[k] = d1[2*k] - d1[2*k+1];
            }
            float Sh3 = (s2[0]+s2[1]) + (s2[2]+s2[3]);
            float s3[2], d3[2];
            s3[0] = d2[0] + d2[1]; d3[0] = d2[0] - d2[1];
            s3[1] = d2[2] + d2[3]; d3[1] = d2[2] - d2[3];
            float Sh7  = s3[0] + s3[1];
            float ShF  = d3[0] + d3[1];
            float Sh1F = d3[0] - d3[1];

            float W0  = wht5(Sh0,  lane);
            float W1  = wht5(Sh1,  lane);
            float W3  = wht5(Sh3,  lane);
            float W7  = wht5(Sh7,  lane);
            float WF  = wht5(ShF,  lane);
            float W1F = wht5(Sh1F, lane);

            float* qp = S->qpart[par][c];
            if      (lane == 3)  qp[1] = W0;
            else if (lane == 7)  qp[2] = W0;
            else if (lane == 15) qp[3] = W0;
            else if (lane == 30) qp[0] = W1F;
            else if (lane == 31) {
                qp[4] = W0; qp[5] = W1; qp[6] = W3;
                qp[7] = W7; qp[8] = WF; qp[9] = W1F;
            }
        }

        if (pf) S->comb_x[(t + 1) & 1][tid] = xpre;
        __syncthreads();

        // ---- LSTM cell update (lanes 0-9 of every warp, redundant) ----
        if (lane < HH) {
            const int h = lane;
            float qf = S->qpart[par][0][h];
            float qi = S->qpart[par][1][h];
            float qg = S->qpart[par][2][h];
            float qo = S->qpart[par][3][h];
            float fg = 1.f / (1.f + expf(-qf));
            float ig = 1.f / (1.f + expf(-qi));
            float gg = tanhf(qg);
            float og = 1.f / (1.f + expf(-qo));
            cx_reg = fg * cx_reg + ig * gg;
            hx_reg = og * tanhf(cx_reg);
            if (c == 0)
                out[((size_t)(t*BB) + b)*HH + h] = hx_reg;
        }
        __syncwarp();
    }

    if (c == 0 && lane < HH) {
        out[(size_t)TT*BB*HH + (size_t)b*HH + lane]                 = hx_reg;
        out[(size_t)TT*BB*HH + (size_t)BB*HH + (size_t)b*HH + lane] = cx_reg;
    }
}

extern "C" void kernel_launch(void* const* d_in, const int* in_sizes, int n_in,
                              void* d_out, int out_size) {
    (void)in_sizes; (void)n_in; (void)out_size;
    const float* inputs  = (const float*)d_in[0];
    const float* qparams = (const float*)d_in[1];
    const float* Wf = (const float*)d_in[2];
    const float* bf = (const float*)d_in[3];
    const float* Wi = (const float*)d_in[4];
    const float* bi = (const float*)d_in[5];
    const float* Wg = (const float*)d_in[6];
    const float* bg = (const float*)d_in[7];
    const float* Wo = (const float*)d_in[8];
    const float* bo = (const float*)d_in[9];
    float* out = (float*)d_out;
    cudaFuncSetAttribute(qlstm_kernel,
                         cudaFuncAttributeMaxDynamicSharedMemorySize,
                         (int)sizeof(Smem));
    qlstm_kernel<<<BB, NTH, sizeof(Smem)>>>(inputs, qparams, Wf, bf, Wi, bi,
                                            Wg, bg, Wo, bo, out);
}